// round 2
// baseline (speedup 1.0000x reference)
#include <cuda_runtime.h>
#include <cuda_bf16.h>

// Problem constants (fixed by the reference)
#define N_ATOMS   2048
#define N_RBF     16
#define N_HIDDEN  32
// centers = linspace(0, 5, 16) -> spacing w = 1/3, gamma = 1/w^2 = 9
// exp(-gamma*t^2) = exp2(-(gamma*log2(e))*t^2)
#define NEG_A     (-12.98425606f)   // -(9 * log2(e))
#define CINV      (0.33333333333333f) // center spacing 1/3

// Fast base-2 exp via MUFU.EX2 (flag-independent, unlike exp2f)
__device__ __forceinline__ float fast_ex2(float x) {
    float r;
    asm("ex2.approx.ftz.f32 %0, %1;" : "=f"(r) : "f"(x));
    return r;
}

// Scratch for per-atom features (device global: no runtime allocation allowed)
__device__ float g_feat[N_ATOMS * N_RBF];

// ---------------------------------------------------------------------------
// Kernel 0: zero the feature scratch and the output scalar
// ---------------------------------------------------------------------------
__global__ void zero_kernel(float* __restrict__ out) {
    int idx = blockIdx.x * blockDim.x + threadIdx.x;
    if (idx < N_ATOMS * N_RBF) g_feat[idx] = 0.0f;
    if (idx == 0) out[0] = 0.0f;
}

// ---------------------------------------------------------------------------
// Kernel 1: pairwise RBF feature accumulation.
// Grid: (N_ATOMS/IB, JCHUNKS). Each thread owns atom i, iterates a j-chunk,
// accumulates feat[16] in registers, then atomicAdds into g_feat.
// ---------------------------------------------------------------------------
#define IB       128                 // atoms (threads) per block
#define JCHUNKS  32
#define JLEN     (N_ATOMS / JCHUNKS) // 64 j's per chunk

__global__ void __launch_bounds__(IB) rbf_kernel(const float* __restrict__ pos) {
    const int i  = blockIdx.x * IB + threadIdx.x;
    const int j0 = blockIdx.y * JLEN;

    const float xi = pos[3 * i + 0];
    const float yi = pos[3 * i + 1];
    const float zi = pos[3 * i + 2];

    float feat[N_RBF];
#pragma unroll
    for (int k = 0; k < N_RBF; k++) feat[k] = 0.0f;

    for (int j = j0; j < j0 + JLEN; j++) {
        // whole warp reads the same j -> L1 broadcast, no smem needed
        const float dx = xi - pos[3 * j + 0];
        const float dy = yi - pos[3 * j + 1];
        const float dz = zi - pos[3 * j + 2];
        const float d2 = dx * dx + dy * dy + dz * dz;
        if (d2 <= 0.0f || d2 >= 25.0f) continue;   // mask (self + cutoff)
        const float d = d2 * __frsqrt_rn(d2);      // MUFU.RSQ + FMUL
#pragma unroll
        for (int k = 0; k < N_RBF; k++) {
            const float t = d - (float)k * CINV;
            feat[k] += fast_ex2(NEG_A * t * t);    // MUFU.EX2
        }
    }

#pragma unroll
    for (int k = 0; k < N_RBF; k++)
        atomicAdd(&g_feat[i * N_RBF + k], feat[k]);
}

// ---------------------------------------------------------------------------
// Kernel 2: per-atom MLP + global sum.
// combined = [feat(16), emb[cs](32)]; h = silu(combined @ W1 + b1);
// e = h @ W2 + b2; out = sum(e)
// ---------------------------------------------------------------------------
#define MLP_BLOCK 256

__global__ void __launch_bounds__(MLP_BLOCK) mlp_kernel(
    const int*   __restrict__ cs,
    const float* __restrict__ emb,
    const float* __restrict__ W1,   // [48][32] row-major
    const float* __restrict__ b1,   // [32]
    const float* __restrict__ W2,   // [32]
    const float* __restrict__ b2,   // [1]
    float* __restrict__ out)
{
    __shared__ float sW1[(N_RBF + N_HIDDEN) * N_HIDDEN];
    __shared__ float sred[MLP_BLOCK];

    const int tid = threadIdx.x;
    for (int idx = tid; idx < (N_RBF + N_HIDDEN) * N_HIDDEN; idx += MLP_BLOCK)
        sW1[idx] = W1[idx];
    __syncthreads();

    const int i   = blockIdx.x * MLP_BLOCK + tid;
    const int csi = (cs[0] < 0) ? 0 : 1;

    float h[N_HIDDEN];
#pragma unroll
    for (int j = 0; j < N_HIDDEN; j++) h[j] = b1[j];

#pragma unroll
    for (int k = 0; k < N_RBF; k++) {
        const float f = g_feat[i * N_RBF + k];
#pragma unroll
        for (int j = 0; j < N_HIDDEN; j++) h[j] += f * sW1[k * N_HIDDEN + j];
    }
#pragma unroll
    for (int m = 0; m < N_HIDDEN; m++) {
        const float e = emb[csi * N_HIDDEN + m];
#pragma unroll
        for (int j = 0; j < N_HIDDEN; j++)
            h[j] += e * sW1[(N_RBF + m) * N_HIDDEN + j];
    }

    float acc = b2[0];
#pragma unroll
    for (int j = 0; j < N_HIDDEN; j++) {
        const float x = h[j];
        const float s = x / (1.0f + __expf(-x));   // silu; large |x| limits correct
        acc += s * W2[j];
    }

    // deterministic in-block tree reduce, then one atomicAdd per block
    sred[tid] = acc;
    __syncthreads();
#pragma unroll
    for (int s = MLP_BLOCK / 2; s > 0; s >>= 1) {
        if (tid < s) sred[tid] += sred[tid + s];
        __syncthreads();
    }
    if (tid == 0) atomicAdd(out, sred[0]);
}

// ---------------------------------------------------------------------------
extern "C" void kernel_launch(void* const* d_in, const int* in_sizes, int n_in,
                              void* d_out, int out_size) {
    const float* pos = (const float*)d_in[0];
    const int*   cs  = (const int*)  d_in[1];
    const float* emb = (const float*)d_in[2];
    const float* W1  = (const float*)d_in[3];
    const float* b1  = (const float*)d_in[4];
    const float* W2  = (const float*)d_in[5];
    const float* b2  = (const float*)d_in[6];
    float* out = (float*)d_out;

    zero_kernel<<<(N_ATOMS * N_RBF + 255) / 256, 256>>>(out);
    rbf_kernel<<<dim3(N_ATOMS / IB, JCHUNKS), IB>>>(pos);
    mlp_kernel<<<N_ATOMS / MLP_BLOCK, MLP_BLOCK>>>(cs, emb, W1, b1, W2, b2, out);
}

// round 3
// speedup vs baseline: 1.6545x; 1.6545x over previous
#include <cuda_runtime.h>
#include <cuda_bf16.h>

// Problem constants (fixed by the reference)
#define N_ATOMS   2048
#define N_RBF     16
#define N_HIDDEN  32
// centers = linspace(0, 5, 16): spacing w = 1/3, gamma = 1/w^2 = 9
// exp(-9 t^2) = exp2(NEG_A * t^2),  NEG_A = -9*log2(e)
#define NEG_A     (-12.984255368f)
#define CW        (0.3333333433f)    // 1.0f/3.0f rounded like fp32 linspace spacing
#define LOG2E     (1.4426950408889634f)

#define WARPS_PER_BLOCK 4
#define BLOCK     (32 * WARPS_PER_BLOCK)          // 128 threads
#define NBLOCKS   (N_ATOMS / WARPS_PER_BLOCK)     // 512 blocks, warp-per-atom

// per-block partial sums (no runtime alloc allowed)
__device__ float g_bsum[NBLOCKS];

__device__ __forceinline__ float fast_ex2(float x) {
    float r; asm("ex2.approx.ftz.f32 %0, %1;" : "=f"(r) : "f"(x)); return r;
}
__device__ __forceinline__ float fast_rsq(float x) {
    float r; asm("rsqrt.approx.ftz.f32 %0, %1;" : "=f"(r) : "f"(x)); return r;
}
__device__ __forceinline__ float fast_rcp(float x) {
    float r; asm("rcp.approx.ftz.f32 %0, %1;" : "=f"(r) : "f"(x)); return r;
}

// 16-center Gaussian RBF accumulation for one distance d (per lane)
__device__ __forceinline__ void accum_rbf(float d, float feat[N_RBF]) {
#pragma unroll
    for (int k = 0; k < N_RBF; k++) {
        const float t = d - (float)k * CW;
        feat[k] += fast_ex2((NEG_A * t) * t);   // 1 MUFU.EX2 + 3 FMA-class
    }
}

__global__ void __launch_bounds__(BLOCK) fused_kernel(
    const float* __restrict__ pos,
    const int*   __restrict__ cs,
    const float* __restrict__ emb,
    const float* __restrict__ W1,   // [48][32] row-major
    const float* __restrict__ b1,   // [32]
    const float* __restrict__ W2,   // [32]
    const float* __restrict__ b2)   // [1]
{
    __shared__ float sx[N_ATOMS], sy[N_ATOMS], sz[N_ATOMS];
    __shared__ float sW1[(N_RBF + N_HIDDEN) * N_HIDDEN];
    __shared__ float sbuf[WARPS_PER_BLOCK][64];   // compacted distances
    __shared__ float sred[WARPS_PER_BLOCK];

    const int tid  = threadIdx.x;
    const int wid  = tid >> 5;
    const int lane = tid & 31;

    // Stage positions (SoA) and W1 into shared memory
    for (int idx = tid; idx < N_ATOMS; idx += BLOCK) {
        sx[idx] = pos[3 * idx + 0];
        sy[idx] = pos[3 * idx + 1];
        sz[idx] = pos[3 * idx + 2];
    }
    for (int idx = tid; idx < (N_RBF + N_HIDDEN) * N_HIDDEN; idx += BLOCK)
        sW1[idx] = W1[idx];
    __syncthreads();

    const int i = blockIdx.x * WARPS_PER_BLOCK + wid;   // this warp's atom
    const float xi = sx[i], yi = sy[i], zi = sz[i];

    float feat[N_RBF];
#pragma unroll
    for (int k = 0; k < N_RBF; k++) feat[k] = 0.0f;

    float* buf = sbuf[wid];
    int cnt = 0;

    // ---- pairwise pass: distance + warp compaction, dense exp batches ----
    for (int j0 = 0; j0 < N_ATOMS; j0 += 32) {
        const int j = j0 + lane;
        const float dx = xi - sx[j];
        const float dy = yi - sy[j];
        const float dz = zi - sz[j];
        const float d2 = dx * dx + dy * dy + dz * dz;
        const bool pass = (d2 > 0.0f) && (d2 < 25.0f);
        const unsigned m = __ballot_sync(0xFFFFFFFFu, pass);
        if (pass) {
            const int rank = __popc(m & ((1u << lane) - 1u));
            buf[cnt + rank] = d2 * fast_rsq(d2);    // d = sqrt(d2)
        }
        cnt += __popc(m);
        __syncwarp();
        if (cnt >= 32) {                             // flush a dense batch
            const float d = buf[lane];
            accum_rbf(d, feat);
            const int rem = cnt - 32;
            const float carry = (lane < rem) ? buf[32 + lane] : 0.0f;
            __syncwarp();
            if (lane < rem) buf[lane] = carry;
            cnt = rem;
            __syncwarp();
        }
    }
    // tail (cnt < 32): inactive lanes get a huge d -> exp underflows to 0
    if (cnt > 0) {
        const float d = (lane < cnt) ? buf[lane] : 1.0e9f;
        accum_rbf(d, feat);
    }

    // ---- warp-reduce features: every lane ends with the full sums ----
#pragma unroll
    for (int k = 0; k < N_RBF; k++) {
        float v = feat[k];
        v += __shfl_xor_sync(0xFFFFFFFFu, v, 16);
        v += __shfl_xor_sync(0xFFFFFFFFu, v, 8);
        v += __shfl_xor_sync(0xFFFFFFFFu, v, 4);
        v += __shfl_xor_sync(0xFFFFFFFFu, v, 2);
        v += __shfl_xor_sync(0xFFFFFFFFu, v, 1);
        feat[k] = v;
    }

    // ---- fused MLP: lane = hidden unit ----
    const int csi = (cs[0] < 0) ? 0 : 1;
    float h = b1[lane];
#pragma unroll
    for (int k = 0; k < N_RBF; k++)
        h = fmaf(feat[k], sW1[k * N_HIDDEN + lane], h);
#pragma unroll
    for (int mrow = 0; mrow < N_HIDDEN; mrow++)
        h = fmaf(emb[csi * N_HIDDEN + mrow], sW1[(N_RBF + mrow) * N_HIDDEN + lane], h);

    // silu(h) = h / (1 + e^{-h})
    const float s = h * fast_rcp(1.0f + fast_ex2(-LOG2E * h));
    float e = s * W2[lane];
    e += __shfl_xor_sync(0xFFFFFFFFu, e, 16);
    e += __shfl_xor_sync(0xFFFFFFFFu, e, 8);
    e += __shfl_xor_sync(0xFFFFFFFFu, e, 4);
    e += __shfl_xor_sync(0xFFFFFFFFu, e, 2);
    e += __shfl_xor_sync(0xFFFFFFFFu, e, 1);

    if (lane == 0) sred[wid] = e + b2[0];
    __syncthreads();
    if (tid == 0) {
        float acc = 0.0f;
#pragma unroll
        for (int wv = 0; wv < WARPS_PER_BLOCK; wv++) acc += sred[wv];
        g_bsum[blockIdx.x] = acc;     // plain store: deterministic
    }
}

// final deterministic reduction of 512 block partials
__global__ void __launch_bounds__(NBLOCKS) reduce_kernel(float* __restrict__ out) {
    __shared__ float sr[NBLOCKS];
    const int tid = threadIdx.x;
    sr[tid] = g_bsum[tid];
    __syncthreads();
#pragma unroll
    for (int s = NBLOCKS / 2; s > 0; s >>= 1) {
        if (tid < s) sr[tid] += sr[tid + s];
        __syncthreads();
    }
    if (tid == 0) out[0] = sr[0];
}

extern "C" void kernel_launch(void* const* d_in, const int* in_sizes, int n_in,
                              void* d_out, int out_size) {
    const float* pos = (const float*)d_in[0];
    const int*   cs  = (const int*)  d_in[1];
    const float* emb = (const float*)d_in[2];
    const float* W1  = (const float*)d_in[3];
    const float* b1  = (const float*)d_in[4];
    const float* W2  = (const float*)d_in[5];
    const float* b2  = (const float*)d_in[6];
    float* out = (float*)d_out;

    fused_kernel<<<NBLOCKS, BLOCK>>>(pos, cs, emb, W1, b1, W2, b2);
    reduce_kernel<<<1, NBLOCKS>>>(out);
}

// round 4
// speedup vs baseline: 2.1587x; 1.3048x over previous
#include <cuda_runtime.h>
#include <cuda_bf16.h>

// Problem constants (fixed by the reference)
#define N_ATOMS   2048
#define N_RBF     16
#define N_HIDDEN  32
// centers c_k = k/3 (linspace(0,5,16)), gamma = 9.
// exp(-9 (d-c_k)^2) = exp2( -9L d^2 + (6L k) d - L k^2 ),  L = log2(e)
#define LOG2E     (1.4426950408889634f)
#define NEG9L     (-12.98425537f)     // -9*log2(e)

#define WARPS_PER_BLOCK 4
#define BLOCK     (32 * WARPS_PER_BLOCK)          // 128 threads
#define NBLOCKS   (N_ATOMS / WARPS_PER_BLOCK)     // 512 blocks, warp-per-atom

// device scratch (no runtime alloc allowed); zero-initialized at module load
__device__ float        g_bsum[NBLOCKS];
__device__ unsigned int g_count;

__device__ __forceinline__ float fast_ex2(float x) {
    float r; asm("ex2.approx.ftz.f32 %0, %1;" : "=f"(r) : "f"(x)); return r;
}
__device__ __forceinline__ float fast_rsq(float x) {
    float r; asm("rsqrt.approx.ftz.f32 %0, %1;" : "=f"(r) : "f"(x)); return r;
}
__device__ __forceinline__ float fast_rcp(float x) {
    float r; asm("rcp.approx.ftz.f32 %0, %1;" : "=f"(r) : "f"(x)); return r;
}

// 16-center Gaussian RBF for one compacted pair: input d^2.
// E_k = a + C0[k] + d*C1[k], a = -9L*d^2, C1[k]=6L*k, C0[k]=-L*k^2 (folded).
__device__ __forceinline__ void accum_rbf_d2(float d2, float feat[N_RBF]) {
    const float d = d2 * fast_rsq(d2);     // sqrt(d2)
    const float a = NEG9L * d2;
#pragma unroll
    for (int k = 0; k < N_RBF; k++) {
        const float c1 = 6.0f * LOG2E * (float)k;
        const float c0 = -LOG2E * (float)(k * k);
        feat[k] += fast_ex2(fmaf(d, c1, a + c0));   // FADD + FMA + EX2 + FADD
    }
}

__global__ void __launch_bounds__(BLOCK) fused_kernel(
    const float* __restrict__ pos,
    const int*   __restrict__ cs,
    const float* __restrict__ emb,
    const float* __restrict__ W1,   // [48][32] row-major
    const float* __restrict__ b1,   // [32]
    const float* __restrict__ W2,   // [32]
    const float* __restrict__ b2,   // [1]
    float*       __restrict__ out)
{
    __shared__ float sbuf[WARPS_PER_BLOCK][64];   // compacted d^2 values
    __shared__ float sred[WARPS_PER_BLOCK];
    __shared__ float sfin[BLOCK];
    __shared__ bool  isLast;

    const int tid  = threadIdx.x;
    const int wid  = tid >> 5;
    const int lane = tid & 31;

    const int i = blockIdx.x * WARPS_PER_BLOCK + wid;   // this warp's atom
    const float xi = __ldg(&pos[3 * i + 0]);
    const float yi = __ldg(&pos[3 * i + 1]);
    const float zi = __ldg(&pos[3 * i + 2]);

    float feat[N_RBF];
#pragma unroll
    for (int k = 0; k < N_RBF; k++) feat[k] = 0.0f;

    float* buf = sbuf[wid];
    int cnt = 0;

    // ---- pairwise pass: distance + warp compaction, dense exp batches ----
    for (int j0 = 0; j0 < N_ATOMS; j0 += 32) {
        const int j = j0 + lane;
        const float dx = xi - __ldg(&pos[3 * j + 0]);
        const float dy = yi - __ldg(&pos[3 * j + 1]);
        const float dz = zi - __ldg(&pos[3 * j + 2]);
        const float d2 = fmaf(dx, dx, fmaf(dy, dy, dz * dz));
        const bool pass = (d2 > 0.0f) && (d2 < 25.0f);
        const unsigned m = __ballot_sync(0xFFFFFFFFu, pass);
        if (pass) {
            const int rank = __popc(m & ((1u << lane) - 1u));
            buf[cnt + rank] = d2;
        }
        cnt += __popc(m);
        __syncwarp();
        if (cnt >= 32) {                             // flush a dense batch
            const float d2b = buf[lane];
            accum_rbf_d2(d2b, feat);
            const int rem = cnt - 32;
            const float carry = (lane < rem) ? buf[32 + lane] : 0.0f;
            __syncwarp();
            if (lane < rem) buf[lane] = carry;
            cnt = rem;
            __syncwarp();
        }
    }
    // tail: inactive lanes get huge d^2 -> exp2(-huge) == 0
    if (cnt > 0) {
        const float d2b = (lane < cnt) ? buf[lane] : 4.0e9f;
        accum_rbf_d2(d2b, feat);
    }

    // ---- warp-reduce features: every lane ends with the full sums ----
#pragma unroll
    for (int k = 0; k < N_RBF; k++) {
        float v = feat[k];
        v += __shfl_xor_sync(0xFFFFFFFFu, v, 16);
        v += __shfl_xor_sync(0xFFFFFFFFu, v, 8);
        v += __shfl_xor_sync(0xFFFFFFFFu, v, 4);
        v += __shfl_xor_sync(0xFFFFFFFFu, v, 2);
        v += __shfl_xor_sync(0xFFFFFFFFu, v, 1);
        feat[k] = v;
    }

    // ---- fused MLP: lane = hidden unit (W1/emb reads are L1-resident) ----
    const int csi = (__ldg(cs) < 0) ? 0 : 1;
    float h = __ldg(&b1[lane]);
#pragma unroll
    for (int k = 0; k < N_RBF; k++)
        h = fmaf(feat[k], __ldg(&W1[k * N_HIDDEN + lane]), h);
#pragma unroll
    for (int mrow = 0; mrow < N_HIDDEN; mrow++)
        h = fmaf(__ldg(&emb[csi * N_HIDDEN + mrow]),
                 __ldg(&W1[(N_RBF + mrow) * N_HIDDEN + lane]), h);

    // silu(h) = h / (1 + e^{-h})
    const float s = h * fast_rcp(1.0f + fast_ex2(-LOG2E * h));
    float e = s * __ldg(&W2[lane]);
    e += __shfl_xor_sync(0xFFFFFFFFu, e, 16);
    e += __shfl_xor_sync(0xFFFFFFFFu, e, 8);
    e += __shfl_xor_sync(0xFFFFFFFFu, e, 4);
    e += __shfl_xor_sync(0xFFFFFFFFu, e, 2);
    e += __shfl_xor_sync(0xFFFFFFFFu, e, 1);

    if (lane == 0) sred[wid] = e + __ldg(b2);       // per-atom energy (+b2)
    __syncthreads();

    // ---- publish block partial; last block reduces deterministically ----
    if (tid == 0) {
        float acc = 0.0f;
#pragma unroll
        for (int wv = 0; wv < WARPS_PER_BLOCK; wv++) acc += sred[wv];
        g_bsum[blockIdx.x] = acc;
        __threadfence();
        const unsigned v = atomicAdd(&g_count, 1u);
        isLast = (v == (unsigned)(NBLOCKS - 1));
    }
    __syncthreads();

    if (isLast) {
        float acc = 0.0f;
#pragma unroll
        for (int r = 0; r < NBLOCKS / BLOCK; r++)
            acc += __ldcg(&g_bsum[r * BLOCK + tid]);   // L1-bypassing read
        sfin[tid] = acc;
        __syncthreads();
#pragma unroll
        for (int s = BLOCK / 2; s > 0; s >>= 1) {
            if (tid < s) sfin[tid] += sfin[tid + s];
            __syncthreads();
        }
        if (tid == 0) {
            out[0] = sfin[0];
            g_count = 0;                // reset for next graph replay
        }
    }
}

extern "C" void kernel_launch(void* const* d_in, const int* in_sizes, int n_in,
                              void* d_out, int out_size) {
    const float* pos = (const float*)d_in[0];
    const int*   cs  = (const int*)  d_in[1];
    const float* emb = (const float*)d_in[2];
    const float* W1  = (const float*)d_in[3];
    const float* b1  = (const float*)d_in[4];
    const float* W2  = (const float*)d_in[5];
    const float* b2  = (const float*)d_in[6];
    float* out = (float*)d_out;

    fused_kernel<<<NBLOCKS, BLOCK>>>(pos, cs, emb, W1, b1, W2, b2, out);
}